// round 12
// baseline (speedup 1.0000x reference)
#include <cuda_runtime.h>
#include <cuda_fp16.h>
#include <math.h>
#include <stdint.h>

#define DDIM 16
#define KCOMP 32
#define NQSTEPS 10             // quad k16 steps (40 chunks)
#define NSTEPS 11              // + 1 linear step
#define BST 104                // B words per component (88 used; 104%32=8 -> CF)
#define TPB 128
#define XBUF (TPB * DDIM)      // floats per staging buffer
#define LOG_2PI 1.8378770664093453f

// chunk tables: chunk c = 4*s + (kk>>2); quad chunks c=0..39, linear 40..43
#define CHUNK_TABLES \
    const int CI[40] = { 0,0,0,0, 1,1,1,1, 2,2,2,2, 3,3,3,3, \
                         4,4,4,5, 5,5,6,6, 6,7,7,7, \
                         8,8,9,9, 10,10,11,11, 12,13,14,15 }; \
    const int CO[40] = { 0,1,2,3, 0,1,2,3, 0,1,2,3, 0,1,2,3, \
                         1,2,3,1, 2,3,1,2, 3,1,2,3, \
                         2,3,2,3, 2,3,2,3, 3,3,3,3 };

__device__ uint32_t g_B[KCOMP * BST];   // fp16x2-packed weights
__device__ float g_const[KCOMP];
__device__ float g_partial[2048];

__device__ __forceinline__ uint32_t smem_u32(const void* p) {
    uint32_t a;
    asm("{ .reg .u64 t; cvta.to.shared.u64 t, %1; cvt.u32.u64 %0, t; }"
        : "=r"(a) : "l"(p));
    return a;
}
__device__ __forceinline__ uint32_t pack_h2(float lo, float hi) {
    uint32_t r;
    asm("cvt.rn.f16x2.f32 %0, %1, %2;" : "=r"(r) : "f"(hi), "f"(lo));
    return r;
}
__device__ __forceinline__ void ldsv2(uint32_t& a, uint32_t& b, uint32_t addr) {
    asm volatile("ld.shared.v2.b32 {%0, %1}, [%2];" : "=r"(a), "=r"(b) : "r"(addr));
}
__device__ __forceinline__ void ldsv2f(float& a, float& b, uint32_t addr) {
    asm volatile("ld.shared.v2.f32 {%0, %1}, [%2];" : "=f"(a), "=f"(b) : "r"(addr));
}
__device__ __forceinline__ void mma_f16(float* c,
                                        uint32_t a0, uint32_t a1, uint32_t a2, uint32_t a3,
                                        uint32_t b0, uint32_t b1) {
    asm volatile(
        "mma.sync.aligned.m16n8k16.row.col.f32.f16.f16.f32 "
        "{%0,%1,%2,%3}, {%4,%5,%6,%7}, {%8,%9}, {%0,%1,%2,%3};"
        : "+f"(c[0]), "+f"(c[1]), "+f"(c[2]), "+f"(c[3])
        : "r"(a0), "r"(a1), "r"(a2), "r"(a3), "r"(b0), "r"(b1));
}
__device__ __forceinline__ void cp16(uint32_t dst, const void* src) {
    asm volatile("cp.async.ca.shared.global [%0], [%1], 16;"
                 :: "r"(dst), "l"(src) : "memory");
}
__device__ __forceinline__ __half2 dup_half(__half2 v, int hi) {
    return hi ? __high2half2(v) : __low2half2(v);
}

// ---------------------------------------------------------------------------
// Setup: ONE WARP per component (32 blocks x 32 threads). Warp-synchronous.
// cov=AA^T; chol w/ rsqrt; M=L^{-1}; P=M^T M; b=Pmu; fp16x2 pack of g_B.
// ---------------------------------------------------------------------------
__global__ void __launch_bounds__(32, 16)
mog_setup(const float* __restrict__ means,
          const float* __restrict__ cov_parts,
          const float* __restrict__ logw)
{
    const int k = blockIdx.x;
    const int t = threadIdx.x;      // 0..31

    __shared__ float A[DDIM][DDIM];
    __shared__ float C[DDIM][DDIM + 1];
    __shared__ float Mi[DDIM][DDIM + 1];
    __shared__ float P[DDIM][DDIM + 1];
    __shared__ float bv[DDIM];
    __shared__ float rdg[DDIM];
    __shared__ float lgs[DDIM];

    #pragma unroll
    for (int e = 0; e < 8; e++) {
        int idx = t * 8 + e;
        A[idx >> 4][idx & 15] = cov_parts[k * DDIM * DDIM + idx];
    }
    __syncwarp();

    #pragma unroll
    for (int e = 0; e < 8; e++) {
        int idx = t * 8 + e;
        int i = idx >> 4, l = idx & 15;
        float s = 0.f;
        #pragma unroll
        for (int j = 0; j < DDIM; j++) s += A[i][j] * A[l][j];
        C[i][l] = s;
    }
    __syncwarp();

    for (int j = 0; j < DDIM; j++) {
        if (t == j) {
            float d = C[j][j];
            float rs = rsqrtf(d);
            rdg[j] = rs;
            C[j][j] = d * rs;          // = sqrt(d)
        }
        __syncwarp();
        if (t > j && t < DDIM) C[t][j] *= rdg[j];
        __syncwarp();
        if (t > j && t < DDIM) {
            for (int l = j + 1; l <= t; l++) C[t][l] -= C[t][j] * C[l][j];
        }
        __syncwarp();
    }

    if (t < DDIM) {                    // M = L^{-1}, column t
        int c = t;
        for (int i = 0; i < c; i++) Mi[i][c] = 0.f;
        Mi[c][c] = rdg[c];
        for (int i = c + 1; i < DDIM; i++) {
            float s = 0.f;
            for (int j = c; j < i; j++) s += C[i][j] * Mi[j][c];
            Mi[i][c] = -s * rdg[i];
        }
        lgs[t] = __logf(C[t][t]);
    }
    __syncwarp();

    #pragma unroll
    for (int e = 0; e < 8; e++) {      // P = M^T M
        int idx = t * 8 + e;
        int i = idx >> 4, j = idx & 15;
        float s = 0.f;
        #pragma unroll
        for (int l = 0; l < DDIM; l++) s += Mi[l][i] * Mi[l][j];
        P[i][j] = s;
    }
    __syncwarp();

    if (t < DDIM) {                    // b = P mu
        float s = 0.f;
        for (int j = 0; j < DDIM; j++) s += P[t][j] * means[k * DDIM + j];
        bv[t] = s;
    }
    __syncwarp();

    if (t == 0) {
        float muPmu = 0.f, logdet = 0.f;
        #pragma unroll
        for (int i = 0; i < DDIM; i++) {
            muPmu += bv[i] * means[k * DDIM + i];
            logdet += lgs[i];
        }
        float lw = logw[k];
        g_const[k] = -0.5f * muPmu - logdet - 0.5f * (float)DDIM * LOG_2PI + lw * lw;
    }
    __syncwarp();

    for (int w = t; w < NSTEPS * 8; w += 32) {
        CHUNK_TABLES
        const int s  = w >> 3;
        const int r  = w & 7;
        const int wp = r >> 1;
        const int hh = r & 1;
        float cf[2];
        #pragma unroll
        for (int e = 0; e < 2; e++) {
            const int kk = hh * 8 + 2 * wp + e;
            float coeff = 0.f;
            if (s < NQSTEPS) {
                const int c = 4 * s + (kk >> 2);
                const int i = CI[c];
                const int j = CO[c] * 4 + (kk & 3);
                if (j > i)       coeff = -P[i][j];
                else if (j == i) coeff = -0.5f * P[i][i];
            } else {
                coeff = bv[kk];
            }
            cf[e] = coeff;
        }
        g_B[k * BST + s * 8 + 2 * wp + hh] = pack_h2(cf[0], cf[1]);
    }
}

// ---------------------------------------------------------------------------
// Main: persistent CTAs, 128 threads = 4 warps, 5 CTAs/SM (register-slim).
// Arithmetic identical to the 4-CTA half2 version; xq cache removed (SEL
// chains from xh), kc consts moved to smem. 11 k16 steps, 88 HMMA/warp-iter.
// ---------------------------------------------------------------------------
__global__ void __launch_bounds__(TPB, 5)
mog_main(const float* __restrict__ data, int N, int nIt, int grid)
{
    __shared__ uint32_t Bsh[KCOMP * BST];
    __shared__ float s_kc[KCOMP];
    __shared__ float sx[2][XBUF];
    __shared__ float s_red[TPB];

    const int tid  = threadIdx.x;
    const int lane = tid & 31;
    const int warp = tid >> 5;
    const int gr   = lane >> 2;     // 0..7
    const int tg   = lane & 3;      // 0..3
    const bool p2  = (tg < 2);
    const int podd = (tg & 1);

    for (int i = tid; i < KCOMP * BST; i += TPB) Bsh[i] = g_B[i];
    if (tid < KCOMP) s_kc[tid] = g_const[tid];
    __syncthreads();

    const uint32_t bBase = smem_u32(Bsh);
    const uint32_t bRd  = bBase + ((uint32_t)gr * BST + 2u * (uint32_t)tg) * 4u;
    const uint32_t kcRd = smem_u32(s_kc) + 8u * (uint32_t)tg;   // float2 at 2tg
    const uint32_t sxB  = smem_u32(sx);
    const uint32_t myDst = sxB + (uint32_t)tid * 64u;            // producer slot

    float acc = 0.f;
    int buf = 0;

    // prologue: stage first tile
    {
        int idxp = blockIdx.x * TPB + tid;
        int pt = idxp < N ? idxp : N - 1;
        const char* g = (const char*)(data + (size_t)pt * DDIM);
        #pragma unroll
        for (int v = 0; v < 4; v++) cp16(myDst + 16u * v, g + 16 * v);
        asm volatile("cp.async.commit_group;" ::: "memory");
    }

    for (int tile = blockIdx.x; tile < nIt; tile += grid) {
        // ---- stage NEXT tile into other buffer ----
        {
            int nxt = tile + grid;
            if (nxt < nIt) {
                int idxp = nxt * TPB + tid;
                int pt = idxp < N ? idxp : N - 1;
                const char* g = (const char*)(data + (size_t)pt * DDIM);
                uint32_t d = myDst + (uint32_t)(buf ^ 1) * (XBUF * 4u);
                #pragma unroll
                for (int v = 0; v < 4; v++) cp16(d + 16u * v, g + 16 * v);
            }
            asm volatile("cp.async.commit_group;" ::: "memory");
        }
        asm volatile("cp.async.wait_group 1;" ::: "memory");
        __syncwarp();

        const int base = tile * TPB + warp * 32;

        // ---- read 4 points, convert to half2 pairs xh[p][i] = {x2i, x2i+1} ----
        __half2 xh[4][8];
        #pragma unroll
        for (int p = 0; p < 4; p++) {
            const float4* s =
                (const float4*)&sx[buf][(warp * 32 + gr + 8 * p) * DDIM];
            #pragma unroll
            for (int v4 = 0; v4 < 4; v4++) {
                float4 f = s[v4];
                xh[p][2 * v4]     = __floats2half2_rn(f.x, f.y);
                xh[p][2 * v4 + 1] = __floats2half2_rn(f.z, f.w);
            }
        }
        __syncwarp();
        buf ^= 1;

        float c[2][4][4];
        #pragma unroll
        for (int t2 = 0; t2 < 2; t2++)
            #pragma unroll
            for (int n = 0; n < 4; n++)
                #pragma unroll
                for (int q = 0; q < 4; q++) c[t2][n][q] = 0.f;

        // ---- 10 quad k16-steps + 1 linear step ----
        CHUNK_TABLES
        #pragma unroll
        for (int s = 0; s < NQSTEPS; s++) {
            uint32_t a[2][4];
            #pragma unroll
            for (int h = 0; h < 2; h++) {
                const int cA = 4 * s + 2 * h;      // chunk if p2
                const int cB = cA + 1;             // chunk if !p2
                const int iA = CI[cA], iB = CI[cB];
                const int oA = CO[cA], oB = CO[cB];
                #pragma unroll
                for (int t2 = 0; t2 < 2; t2++) {
                    #pragma unroll
                    for (int pp = 0; pp < 2; pp++) {
                        const int p = t2 * 2 + pp;
                        __half2 xi2;
                        if (iA == iB) {
                            xi2 = dup_half(xh[p][iA >> 1], iA & 1);
                        } else {
                            __half2 dA = dup_half(xh[p][iA >> 1], iA & 1);
                            __half2 dB = dup_half(xh[p][iB >> 1], iB & 1);
                            xi2 = p2 ? dA : dB;
                        }
                        __half2 xv;
                        if (oA == oB) {
                            xv = podd ? xh[p][2 * oA + 1] : xh[p][2 * oA];
                        } else {
                            __half2 vA = podd ? xh[p][2 * oA + 1] : xh[p][2 * oA];
                            __half2 vB = podd ? xh[p][2 * oB + 1] : xh[p][2 * oB];
                            xv = p2 ? vA : vB;
                        }
                        __half2 prod = __hmul2(xi2, xv);
                        a[t2][pp + 2 * h] = *(uint32_t*)&prod;
                    }
                }
            }
            #pragma unroll
            for (int n = 0; n < 4; n++) {
                uint32_t b0, b1;
                ldsv2(b0, b1, bRd + ((uint32_t)(n * 8) * BST + (uint32_t)s * 8u) * 4u);
                mma_f16(c[0][n], a[0][0], a[0][1], a[0][2], a[0][3], b0, b1);
                mma_f16(c[1][n], a[1][0], a[1][1], a[1][2], a[1][3], b0, b1);
            }
        }
        {   // linear step s = 10: fragments = xh selected by (p2, podd)
            uint32_t a[2][4];
            #pragma unroll
            for (int t2 = 0; t2 < 2; t2++) {
                #pragma unroll
                for (int pp = 0; pp < 2; pp++) {
                    const int p = t2 * 2 + pp;
                    __half2 vA0 = podd ? xh[p][1] : xh[p][0];
                    __half2 vB0 = podd ? xh[p][3] : xh[p][2];
                    __half2 vA1 = podd ? xh[p][5] : xh[p][4];
                    __half2 vB1 = podd ? xh[p][7] : xh[p][6];
                    __half2 v0 = p2 ? vA0 : vB0;
                    __half2 v1 = p2 ? vA1 : vB1;
                    a[t2][pp]     = *(uint32_t*)&v0;
                    a[t2][pp + 2] = *(uint32_t*)&v1;
                }
            }
            #pragma unroll
            for (int n = 0; n < 4; n++) {
                uint32_t b0, b1;
                ldsv2(b0, b1, bRd + ((uint32_t)(n * 8) * BST + 80u) * 4u);
                mma_f16(c[0][n], a[0][0], a[0][1], a[0][2], a[0][3], b0, b1);
                mma_f16(c[1][n], a[1][0], a[1][1], a[1][2], a[1][3], b0, b1);
            }
        }

        // ---- epilogue: add per-component const (from smem), exp, logsumexp ----
        #pragma unroll
        for (int t2 = 0; t2 < 2; t2++) {
            float S0 = 0.f, S1 = 0.f;
            #pragma unroll
            for (int n = 0; n < 4; n++) {
                float k0, k1;
                ldsv2f(k0, k1, kcRd + (uint32_t)(n * 32));
                S0 += __expf(c[t2][n][0] + k0) + __expf(c[t2][n][1] + k1);
                S1 += __expf(c[t2][n][2] + k0) + __expf(c[t2][n][3] + k1);
            }
            S0 += __shfl_xor_sync(0xffffffffu, S0, 1);
            S0 += __shfl_xor_sync(0xffffffffu, S0, 2);
            S1 += __shfl_xor_sync(0xffffffffu, S1, 1);
            S1 += __shfl_xor_sync(0xffffffffu, S1, 2);
            if (tg == 0) {
                int r0 = base + t2 * 16 + gr;
                if (r0 < N)     acc += __logf(S0);
                if (r0 + 8 < N) acc += __logf(S1);
            }
        }
    }

    s_red[tid] = acc;
    __syncthreads();
    for (int s = TPB / 2; s > 0; s >>= 1) {
        if (tid < s) s_red[tid] += s_red[tid + s];
        __syncthreads();
    }
    if (tid == 0) g_partial[blockIdx.x] = s_red[0];
}

// ---------------------------------------------------------------------------
__global__ void mog_final(float* __restrict__ out, int N, int nBlocks)
{
    __shared__ double red[256];
    double s = 0.0;
    for (int i = threadIdx.x; i < nBlocks; i += 256) s += (double)g_partial[i];
    red[threadIdx.x] = s;
    __syncthreads();
    for (int st = 128; st > 0; st >>= 1) {
        if (threadIdx.x < st) red[threadIdx.x] += red[threadIdx.x + st];
        __syncthreads();
    }
    if (threadIdx.x == 0) out[0] = (float)(red[0] / (double)N);
}

// ---------------------------------------------------------------------------
extern "C" void kernel_launch(void* const* d_in, const int* in_sizes, int n_in,
                              void* d_out, int out_size)
{
    const float* data      = (const float*)d_in[0];
    const float* means     = (const float*)d_in[1];
    const float* cov_parts = (const float*)d_in[2];
    const float* logw      = (const float*)d_in[3];
    float* out = (float*)d_out;

    const int N = in_sizes[0] / DDIM;

    int sm = 148;
    cudaDeviceGetAttribute(&sm, cudaDevAttrMultiProcessorCount, 0);
    if (sm > 680) sm = 680;

    const int nIt = (N + TPB - 1) / TPB;
    int grid = sm * 5;
    if (grid > nIt) grid = nIt;
    if (grid > 2048) grid = 2048;

    mog_setup<<<KCOMP, 32>>>(means, cov_parts, logw);
    mog_main<<<grid, TPB>>>(data, N, nIt, grid);
    mog_final<<<1, 256>>>(out, N, grid);
}

// round 13
// speedup vs baseline: 1.3908x; 1.3908x over previous
#include <cuda_runtime.h>
#include <cuda_fp16.h>
#include <math.h>
#include <stdint.h>

#define DDIM 16
#define KCOMP 32
#define NQSTEPS 10             // quad k16 steps (40 chunks)
#define NSTEPS 11              // + 1 linear step
#define BST 104                // B words per component (88 used; 104%32=8 -> CF)
#define TPB 128
#define XSTRIDE 20             // staging stride in words (80B: conflict-free)
#define XBUF (TPB * XSTRIDE)   // floats per staging buffer
#define LOG_2PI 1.8378770664093453f
#define LOG2E 1.4426950408889634f
#define LN2F 0.6931471805599453f

// chunk tables: chunk c = 4*s + (kk>>2); quad chunks c=0..39, linear 40..43
#define CHUNK_TABLES \
    const int CI[40] = { 0,0,0,0, 1,1,1,1, 2,2,2,2, 3,3,3,3, \
                         4,4,4,5, 5,5,6,6, 6,7,7,7, \
                         8,8,9,9, 10,10,11,11, 12,13,14,15 }; \
    const int CO[40] = { 0,1,2,3, 0,1,2,3, 0,1,2,3, 0,1,2,3, \
                         1,2,3,1, 2,3,1,2, 3,1,2,3, \
                         2,3,2,3, 2,3,2,3, 3,3,3,3 };

__device__ uint32_t g_B[KCOMP * BST];   // fp16x2 weights, pre-scaled by log2e
__device__ float g_const[KCOMP];        // consts, pre-scaled by log2e
__device__ float g_partial[2048];

__device__ __forceinline__ uint32_t smem_u32(const void* p) {
    uint32_t a;
    asm("{ .reg .u64 t; cvta.to.shared.u64 t, %1; cvt.u32.u64 %0, t; }"
        : "=r"(a) : "l"(p));
    return a;
}
__device__ __forceinline__ uint32_t pack_h2(float lo, float hi) {
    uint32_t r;
    asm("cvt.rn.f16x2.f32 %0, %1, %2;" : "=r"(r) : "f"(hi), "f"(lo));
    return r;
}
__device__ __forceinline__ float ex2f(float x) {
    float r;
    asm("ex2.approx.ftz.f32 %0, %1;" : "=f"(r) : "f"(x));
    return r;
}
__device__ __forceinline__ float lg2f(float x) {
    float r;
    asm("lg2.approx.ftz.f32 %0, %1;" : "=f"(r) : "f"(x));
    return r;
}
__device__ __forceinline__ void ldsv2(uint32_t& a, uint32_t& b, uint32_t addr) {
    asm volatile("ld.shared.v2.b32 {%0, %1}, [%2];" : "=r"(a), "=r"(b) : "r"(addr));
}
__device__ __forceinline__ void mma_f16(float* c,
                                        uint32_t a0, uint32_t a1, uint32_t a2, uint32_t a3,
                                        uint32_t b0, uint32_t b1) {
    asm volatile(
        "mma.sync.aligned.m16n8k16.row.col.f32.f16.f16.f32 "
        "{%0,%1,%2,%3}, {%4,%5,%6,%7}, {%8,%9}, {%0,%1,%2,%3};"
        : "+f"(c[0]), "+f"(c[1]), "+f"(c[2]), "+f"(c[3])
        : "r"(a0), "r"(a1), "r"(a2), "r"(a3), "r"(b0), "r"(b1));
}
__device__ __forceinline__ void cp16(uint32_t dst, const void* src) {
    asm volatile("cp.async.ca.shared.global [%0], [%1], 16;"
                 :: "r"(dst), "l"(src) : "memory");
}
__device__ __forceinline__ __half2 dup_half(__half2 v, int hi) {
    return hi ? __high2half2(v) : __low2half2(v);
}

// ---------------------------------------------------------------------------
// Setup: ONE WARP per component. cov=AA^T; chol w/ rsqrt; M=L^{-1}; P=M^T M;
// b=Pmu. Weights and consts are PRE-SCALED BY log2e (exp2-domain scoring).
// ---------------------------------------------------------------------------
__global__ void __launch_bounds__(32, 16)
mog_setup(const float* __restrict__ means,
          const float* __restrict__ cov_parts,
          const float* __restrict__ logw)
{
    const int k = blockIdx.x;
    const int t = threadIdx.x;      // 0..31

    __shared__ float A[DDIM][DDIM];
    __shared__ float C[DDIM][DDIM + 1];
    __shared__ float Mi[DDIM][DDIM + 1];
    __shared__ float P[DDIM][DDIM + 1];
    __shared__ float bv[DDIM];
    __shared__ float rdg[DDIM];
    __shared__ float lgs[DDIM];

    #pragma unroll
    for (int e = 0; e < 8; e++) {
        int idx = t * 8 + e;
        A[idx >> 4][idx & 15] = cov_parts[k * DDIM * DDIM + idx];
    }
    __syncwarp();

    #pragma unroll
    for (int e = 0; e < 8; e++) {
        int idx = t * 8 + e;
        int i = idx >> 4, l = idx & 15;
        float s = 0.f;
        #pragma unroll
        for (int j = 0; j < DDIM; j++) s += A[i][j] * A[l][j];
        C[i][l] = s;
    }
    __syncwarp();

    for (int j = 0; j < DDIM; j++) {
        if (t == j) {
            float d = C[j][j];
            float rs = rsqrtf(d);
            rdg[j] = rs;
            C[j][j] = d * rs;          // = sqrt(d)
        }
        __syncwarp();
        if (t > j && t < DDIM) C[t][j] *= rdg[j];
        __syncwarp();
        if (t > j && t < DDIM) {
            for (int l = j + 1; l <= t; l++) C[t][l] -= C[t][j] * C[l][j];
        }
        __syncwarp();
    }

    if (t < DDIM) {                    // M = L^{-1}, column t
        int c = t;
        for (int i = 0; i < c; i++) Mi[i][c] = 0.f;
        Mi[c][c] = rdg[c];
        for (int i = c + 1; i < DDIM; i++) {
            float s = 0.f;
            for (int j = c; j < i; j++) s += C[i][j] * Mi[j][c];
            Mi[i][c] = -s * rdg[i];
        }
        lgs[t] = __logf(C[t][t]);
    }
    __syncwarp();

    #pragma unroll
    for (int e = 0; e < 8; e++) {      // P = M^T M
        int idx = t * 8 + e;
        int i = idx >> 4, j = idx & 15;
        float s = 0.f;
        #pragma unroll
        for (int l = 0; l < DDIM; l++) s += Mi[l][i] * Mi[l][j];
        P[i][j] = s;
    }
    __syncwarp();

    if (t < DDIM) {                    // b = P mu
        float s = 0.f;
        for (int j = 0; j < DDIM; j++) s += P[t][j] * means[k * DDIM + j];
        bv[t] = s;
    }
    __syncwarp();

    if (t == 0) {
        float muPmu = 0.f, logdet = 0.f;
        #pragma unroll
        for (int i = 0; i < DDIM; i++) {
            muPmu += bv[i] * means[k * DDIM + i];
            logdet += lgs[i];
        }
        float lw = logw[k];
        float ck = -0.5f * muPmu - logdet - 0.5f * (float)DDIM * LOG_2PI + lw * lw;
        g_const[k] = ck * LOG2E;       // exp2 domain
    }
    __syncwarp();

    for (int w = t; w < NSTEPS * 8; w += 32) {
        CHUNK_TABLES
        const int s  = w >> 3;
        const int r  = w & 7;
        const int wp = r >> 1;
        const int hh = r & 1;
        float cf[2];
        #pragma unroll
        for (int e = 0; e < 2; e++) {
            const int kk = hh * 8 + 2 * wp + e;
            float coeff = 0.f;
            if (s < NQSTEPS) {
                const int c = 4 * s + (kk >> 2);
                const int i = CI[c];
                const int j = CO[c] * 4 + (kk & 3);
                if (j > i)       coeff = -P[i][j];
                else if (j == i) coeff = -0.5f * P[i][i];
            } else {
                coeff = bv[kk];
            }
            cf[e] = coeff * LOG2E;     // exp2 domain
        }
        g_B[k * BST + s * 8 + 2 * wp + hh] = pack_h2(cf[0], cf[1]);
    }
}

// ---------------------------------------------------------------------------
// Main: persistent CTAs, 128 threads = 4 warps, 4 CTAs/SM. Half2-native
// fragments (R11 base); exp2-domain epilogue with pairwise tree sums;
// 80B-stride staging (conflict-free LDS.128). 11 k16 steps, 88 HMMA.
// ---------------------------------------------------------------------------
__global__ void __launch_bounds__(TPB, 4)
mog_main(const float* __restrict__ data, int N, int nIt, int grid)
{
    __shared__ uint32_t Bsh[KCOMP * BST];
    __shared__ float sx[2][XBUF];
    __shared__ float s_red[TPB];

    const int tid  = threadIdx.x;
    const int lane = tid & 31;
    const int warp = tid >> 5;
    const int gr   = lane >> 2;     // 0..7
    const int tg   = lane & 3;      // 0..3
    const bool p2  = (tg < 2);
    const int podd = (tg & 1);

    for (int i = tid; i < KCOMP * BST; i += TPB) Bsh[i] = g_B[i];

    float kc[4][2];
    #pragma unroll
    for (int n = 0; n < 4; n++) {
        kc[n][0] = g_const[n * 8 + 2 * tg];
        kc[n][1] = g_const[n * 8 + 2 * tg + 1];
    }
    __syncthreads();

    const uint32_t bBase = smem_u32(Bsh);
    const uint32_t bRd = bBase + ((uint32_t)gr * BST + 2u * (uint32_t)tg) * 4u;
    const uint32_t sxB  = smem_u32(sx);
    const uint32_t myDst = sxB + (uint32_t)tid * (XSTRIDE * 4u); // producer slot

    float acc = 0.f;
    int buf = 0;

    // prologue: stage first tile
    {
        int idxp = blockIdx.x * TPB + tid;
        int pt = idxp < N ? idxp : N - 1;
        const char* g = (const char*)(data + (size_t)pt * DDIM);
        #pragma unroll
        for (int v = 0; v < 4; v++) cp16(myDst + 16u * v, g + 16 * v);
        asm volatile("cp.async.commit_group;" ::: "memory");
    }

    for (int tile = blockIdx.x; tile < nIt; tile += grid) {
        // ---- stage NEXT tile into other buffer ----
        {
            int nxt = tile + grid;
            if (nxt < nIt) {
                int idxp = nxt * TPB + tid;
                int pt = idxp < N ? idxp : N - 1;
                const char* g = (const char*)(data + (size_t)pt * DDIM);
                uint32_t d = myDst + (uint32_t)(buf ^ 1) * (XBUF * 4u);
                #pragma unroll
                for (int v = 0; v < 4; v++) cp16(d + 16u * v, g + 16 * v);
            }
            asm volatile("cp.async.commit_group;" ::: "memory");
        }
        asm volatile("cp.async.wait_group 1;" ::: "memory");
        __syncwarp();

        const int base = tile * TPB + warp * 32;

        // ---- read 4 points, convert to half2 pairs xh[p][i] = {x2i, x2i+1} ----
        __half2 xh[4][8];
        #pragma unroll
        for (int p = 0; p < 4; p++) {
            const float4* s =
                (const float4*)&sx[buf][(warp * 32 + gr + 8 * p) * XSTRIDE];
            #pragma unroll
            for (int v4 = 0; v4 < 4; v4++) {
                float4 f = s[v4];
                xh[p][2 * v4]     = __floats2half2_rn(f.x, f.y);
                xh[p][2 * v4 + 1] = __floats2half2_rn(f.z, f.w);
            }
        }
        __syncwarp();
        buf ^= 1;

        // ---- per-thread j-pair: xq[p][m] = {x[4m+2podd], x[4m+2podd+1]} ----
        __half2 xq[4][4];
        #pragma unroll
        for (int p = 0; p < 4; p++) {
            #pragma unroll
            for (int m = 0; m < 4; m++) {
                xq[p][m] = podd ? xh[p][2 * m + 1] : xh[p][2 * m];
            }
        }

        float c[2][4][4];
        #pragma unroll
        for (int t2 = 0; t2 < 2; t2++)
            #pragma unroll
            for (int n = 0; n < 4; n++)
                #pragma unroll
                for (int q = 0; q < 4; q++) c[t2][n][q] = 0.f;

        // ---- 10 quad k16-steps + 1 linear step ----
        CHUNK_TABLES
        #pragma unroll
        for (int s = 0; s < NQSTEPS; s++) {
            uint32_t a[2][4];
            #pragma unroll
            for (int h = 0; h < 2; h++) {
                const int cA = 4 * s + 2 * h;      // chunk if p2
                const int cB = cA + 1;             // chunk if !p2
                const int iA = CI[cA], iB = CI[cB];
                const int oA = CO[cA], oB = CO[cB];
                #pragma unroll
                for (int t2 = 0; t2 < 2; t2++) {
                    #pragma unroll
                    for (int pp = 0; pp < 2; pp++) {
                        const int p = t2 * 2 + pp;
                        __half2 xi2;
                        if (iA == iB) {
                            xi2 = dup_half(xh[p][iA >> 1], iA & 1);
                        } else {
                            __half2 dA = dup_half(xh[p][iA >> 1], iA & 1);
                            __half2 dB = dup_half(xh[p][iB >> 1], iB & 1);
                            xi2 = p2 ? dA : dB;
                        }
                        __half2 xv = (oA == oB) ? xq[p][oA]
                                                : (p2 ? xq[p][oA] : xq[p][oB]);
                        __half2 prod = __hmul2(xi2, xv);
                        a[t2][pp + 2 * h] = *(uint32_t*)&prod;
                    }
                }
            }
            #pragma unroll
            for (int n = 0; n < 4; n++) {
                uint32_t b0, b1;
                ldsv2(b0, b1, bRd + ((uint32_t)(n * 8) * BST + (uint32_t)s * 8u) * 4u);
                mma_f16(c[0][n], a[0][0], a[0][1], a[0][2], a[0][3], b0, b1);
                mma_f16(c[1][n], a[1][0], a[1][1], a[1][2], a[1][3], b0, b1);
            }
        }
        {   // linear step s = 10: fragments are xq pairs directly
            uint32_t a[2][4];
            #pragma unroll
            for (int t2 = 0; t2 < 2; t2++) {
                #pragma unroll
                for (int pp = 0; pp < 2; pp++) {
                    const int p = t2 * 2 + pp;
                    __half2 v0 = p2 ? xq[p][0] : xq[p][1];
                    __half2 v1 = p2 ? xq[p][2] : xq[p][3];
                    a[t2][pp]     = *(uint32_t*)&v0;
                    a[t2][pp + 2] = *(uint32_t*)&v1;
                }
            }
            #pragma unroll
            for (int n = 0; n < 4; n++) {
                uint32_t b0, b1;
                ldsv2(b0, b1, bRd + ((uint32_t)(n * 8) * BST + 80u) * 4u);
                mma_f16(c[0][n], a[0][0], a[0][1], a[0][2], a[0][3], b0, b1);
                mma_f16(c[1][n], a[1][0], a[1][1], a[1][2], a[1][3], b0, b1);
            }
        }

        // ---- epilogue: exp2 domain, pairwise tree sums ----
        #pragma unroll
        for (int t2 = 0; t2 < 2; t2++) {
            float e0[8], e1[8];
            #pragma unroll
            for (int n = 0; n < 4; n++) {
                e0[2 * n]     = ex2f(c[t2][n][0] + kc[n][0]);
                e0[2 * n + 1] = ex2f(c[t2][n][1] + kc[n][1]);
                e1[2 * n]     = ex2f(c[t2][n][2] + kc[n][0]);
                e1[2 * n + 1] = ex2f(c[t2][n][3] + kc[n][1]);
            }
            float S0 = ((e0[0] + e0[1]) + (e0[2] + e0[3]))
                     + ((e0[4] + e0[5]) + (e0[6] + e0[7]));
            float S1 = ((e1[0] + e1[1]) + (e1[2] + e1[3]))
                     + ((e1[4] + e1[5]) + (e1[6] + e1[7]));
            S0 += __shfl_xor_sync(0xffffffffu, S0, 1);
            S0 += __shfl_xor_sync(0xffffffffu, S0, 2);
            S1 += __shfl_xor_sync(0xffffffffu, S1, 1);
            S1 += __shfl_xor_sync(0xffffffffu, S1, 2);
            if (tg == 0) {
                int r0 = base + t2 * 16 + gr;
                if (r0 < N)     acc += lg2f(S0);
                if (r0 + 8 < N) acc += lg2f(S1);
            }
        }
    }

    acc *= LN2F;    // back to natural log, once per thread

    s_red[tid] = acc;
    __syncthreads();
    for (int s = TPB / 2; s > 0; s >>= 1) {
        if (tid < s) s_red[tid] += s_red[tid + s];
        __syncthreads();
    }
    if (tid == 0) g_partial[blockIdx.x] = s_red[0];
}

// ---------------------------------------------------------------------------
__global__ void mog_final(float* __restrict__ out, int N, int nBlocks)
{
    __shared__ double red[256];
    double s = 0.0;
    for (int i = threadIdx.x; i < nBlocks; i += 256) s += (double)g_partial[i];
    red[threadIdx.x] = s;
    __syncthreads();
    for (int st = 128; st > 0; st >>= 1) {
        if (threadIdx.x < st) red[threadIdx.x] += red[threadIdx.x + st];
        __syncthreads();
    }
    if (threadIdx.x == 0) out[0] = (float)(red[0] / (double)N);
}

// ---------------------------------------------------------------------------
extern "C" void kernel_launch(void* const* d_in, const int* in_sizes, int n_in,
                              void* d_out, int out_size)
{
    const float* data      = (const float*)d_in[0];
    const float* means     = (const float*)d_in[1];
    const float* cov_parts = (const float*)d_in[2];
    const float* logw      = (const float*)d_in[3];
    float* out = (float*)d_out;

    const int N = in_sizes[0] / DDIM;

    int sm = 148;
    cudaDeviceGetAttribute(&sm, cudaDevAttrMultiProcessorCount, 0);
    if (sm > 680) sm = 680;

    const int nIt = (N + TPB - 1) / TPB;
    int grid = sm * 4;
    if (grid > nIt) grid = nIt;
    if (grid > 2048) grid = 2048;

    mog_setup<<<KCOMP, 32>>>(means, cov_parts, logw);
    mog_main<<<grid, TPB>>>(data, N, nIt, grid);
    mog_final<<<1, 256>>>(out, N, grid);
}